// round 6
// baseline (speedup 1.0000x reference)
#include <cuda_runtime.h>
#include <cuda_fp16.h>
#include <math.h>

#define BATCH 4
#define S 160
#define SS (S*S)
#define VOX (S*S*S)
#define TOT (BATCH*VOX)

#define NB12 2560  // 4 chunks x (4 batch x 160 d-planes)
#define NB3  2560  // 4 chunks x (4 batch x 160 h-planes)

// 1D Gaussian taps exp(-t^2/50), t=-4..4
__constant__ float KW[9] = {
  0.72614902f, 0.83527023f, 0.92311633f, 0.98019868f, 1.0f,
  0.98019868f, 0.92311633f, 0.83527023f, 0.72614902f
};
#define KSUM1 7.92946854f

__device__ __half  g_t2[TOT];          // conv-W-H of labels (fp16)
__device__ double  g_p1[NB12][3];      // per-block partial sums: p, x, x*p
__device__ float   g_mean[2][BATCH];   // class means
__device__ double  g_p3[NB3][4];       // per-block partials: n0, d0, n1, d1
__device__ unsigned int g_cnt12;       // zero-init; reset by last block each launch
__device__ unsigned int g_cnt3;

__device__ __forceinline__ float edge_sum(int c){
  if (c >= 4 && c < S - 4) return KSUM1;
  float s = 0.f;
  #pragma unroll
  for (int t = -4; t <= 4; t++){
    int p = c + t;
    if (p >= 0 && p < S) s += KW[t + 4];
  }
  return s;
}

__device__ __forceinline__ double blockReduce160(double v, double* sm){
  int t = threadIdx.x;
  sm[t] = v;
  __syncthreads();
  if (t < 32){
    double s = sm[t] + sm[t+32] + sm[t+64] + sm[t+96] + sm[t+128];
    #pragma unroll
    for (int o = 16; o > 0; o >>= 1) s += __shfl_down_sync(0xffffffffu, s, o);
    if (t == 0) sm[0] = s;
  }
  __syncthreads();
  double r = sm[0];
  __syncthreads();
  return r;
}

// K12: fused conv-W + conv-H of labels for one (b, d, h-chunk) tile,
// plus per-batch partial sums of p, x, x*p. Last block computes class means.
__global__ void __launch_bounds__(160) k12_convwh(const float* __restrict__ lab,
                                                  const float* __restrict__ inp){
  __shared__ float raw[48][168];   // rows h0-4 .. h0+43, cols padded +4 each side
  __shared__ double sred[S];
  __shared__ int islast;
  int w = threadIdx.x;
  int bid = blockIdx.x;
  int chunk = bid & 3;
  int db = bid >> 2;               // b-major: bids [b*640,(b+1)*640) belong to batch b
  int b = db / S, d = db - b * S;
  int h0 = chunk * 40;
  const float* labp = lab + b * VOX + d * SS;
  const float* inpp = inp + b * VOX + d * SS;

  if (w < 8){
    int c = (w < 4) ? w : (160 + w);
    #pragma unroll 4
    for (int r = 0; r < 48; r++) raw[r][c] = 0.f;
  }

  float sp = 0.f, si = 0.f, sip = 0.f;
  #pragma unroll 8
  for (int r = 0; r < 48; r++){
    int h = h0 - 4 + r;
    float l = (h >= 0 && h < S) ? labp[h * S + w] : 0.f;
    raw[r][4 + w] = l;
    if (r >= 4 && r < 44){
      float x = inpp[(h0 + r - 4) * S + w];
      sp += l; si += x; sip = fmaf(l, x, sip);
    }
  }
  __syncthreads();

  float win[9];
  #pragma unroll
  for (int i = 0; i < 9; i++){
    float a = 0.f;
    #pragma unroll
    for (int t = 0; t < 9; t++) a = fmaf(KW[t], raw[i][w + t], a);
    win[i] = a;
  }
  __half* dst = g_t2 + b * VOX + d * SS + h0 * S + w;
  #pragma unroll 4
  for (int j = 0; j < 40; j++){
    float acc = 0.f;
    #pragma unroll
    for (int i = 0; i < 9; i++) acc = fmaf(KW[i], win[i], acc);
    dst[j * S] = __float2half_rn(acc);
    #pragma unroll
    for (int i = 0; i < 8; i++) win[i] = win[i + 1];
    float a = 0.f;
    #pragma unroll
    for (int t = 0; t < 9; t++) a = fmaf(KW[t], raw[j + 9][w + t], a);
    win[8] = a;
  }

  double rp  = blockReduce160((double)sp,  sred);
  double ri  = blockReduce160((double)si,  sred);
  double rip = blockReduce160((double)sip, sred);
  if (w == 0){
    g_p1[bid][0] = rp;
    g_p1[bid][1] = ri;
    g_p1[bid][2] = rip;
    __threadfence();
    unsigned int t = atomicAdd(&g_cnt12, 1u);
    islast = (t == NB12 - 1);
  }
  __syncthreads();
  if (islast){
    for (int bb = 0; bb < BATCH; bb++){
      double ap = 0, ai = 0, aip = 0;
      for (int i = w; i < 640; i += 160){
        ap  += g_p1[bb*640 + i][0];
        ai  += g_p1[bb*640 + i][1];
        aip += g_p1[bb*640 + i][2];
      }
      ap  = blockReduce160(ap,  sred);
      ai  = blockReduce160(ai,  sred);
      aip = blockReduce160(aip, sred);
      if (w == 0){
        double m0 = aip / (ap + 1e-5 * (double)VOX);
        double m1 = (ai - aip) / ((double)VOX - ap + 1e-5 * (double)VOX);
        g_mean[0][bb] = (float)m0;
        g_mean[1][bb] = (float)m1;
      }
    }
    if (w == 0) g_cnt12 = 0;   // reset for next graph replay
  }
}

// K3: conv along D fused with the weighted reduction, MLP-8 batched loads.
// G1 = conv3d(1-p0) = closed-form conv3d(ones) - G0. Last block finalizes out.
__global__ void __launch_bounds__(160) k3_convd_reduce(const float* __restrict__ lab,
                                                       const float* __restrict__ inp,
                                                       float* __restrict__ out){
  __shared__ double sred[S];
  __shared__ int islast;
  int w = threadIdx.x;
  int bid = blockIdx.x;
  int chunk = bid & 3;
  int bh = bid >> 2;
  int b = bh / S, h = bh - b * S;
  int base = b * VOX + h * S + w;
  const __half* src = g_t2 + base;
  float m0 = g_mean[0][b], m1 = g_mean[1][b];
  float se_hw = edge_sum(h) * edge_sum(w);
  int d0 = chunk * 40;
  float win[9];
  #pragma unroll
  for (int i = 0; i < 9; i++){
    int d = d0 - 4 + i;
    win[i] = (d >= 0 && d < S) ? __half2float(src[d * SS]) : 0.f;
  }
  float n0 = 0.f, dn0 = 0.f, n1 = 0.f, dn1 = 0.f;
  for (int g = 0; g < 5; g++){
    int dbse = d0 + g * 8;
    float nv[8], lv[8], xv[8];
    #pragma unroll
    for (int i = 0; i < 8; i++){
      int nd = dbse + 5 + i;
      nv[i] = (nd < S) ? __half2float(src[nd * SS]) : 0.f;
    }
    #pragma unroll
    for (int i = 0; i < 8; i++) lv[i] = lab[base + (dbse + i) * SS];
    #pragma unroll
    for (int i = 0; i < 8; i++) xv[i] = inp[base + (dbse + i) * SS];
    #pragma unroll
    for (int i = 0; i < 8; i++){
      int d = dbse + i;
      float G0 = 0.f;
      #pragma unroll
      for (int k = 0; k < 9; k++) G0 = fmaf(KW[k], win[k], G0);
      float G1 = edge_sum(d) * se_hw - G0;
      float l = lv[i], x = xv[i];
      float q0 = (x - m0) * (x - m0);
      float q1 = (x - m1) * (x - m1);
      float w0 = __expf(-q0 * q0);
      float w1 = __expf(-q1 * q1);
      float t0 = w0 * G0, t1 = w1 * G1;
      n0  = fmaf(l, t0, n0);        dn0 += t0;
      n1  = fmaf(1.f - l, t1, n1);  dn1 += t1;
      #pragma unroll
      for (int k = 0; k < 8; k++) win[k] = win[k + 1];
      win[8] = nv[i];
    }
  }
  double r0 = blockReduce160((double)n0,  sred);
  double r1 = blockReduce160((double)dn0, sred);
  double r2 = blockReduce160((double)n1,  sred);
  double r3 = blockReduce160((double)dn1, sred);
  if (w == 0){
    g_p3[bid][0] = r0; g_p3[bid][1] = r1;
    g_p3[bid][2] = r2; g_p3[bid][3] = r3;
    __threadfence();
    unsigned int t = atomicAdd(&g_cnt3, 1u);
    islast = (t == NB3 - 1);
  }
  __syncthreads();
  if (islast){
    double a0 = 0, a1 = 0, a2 = 0, a3 = 0;
    for (int i = w; i < NB3; i += 160){
      a0 += g_p3[i][0]; a1 += g_p3[i][1];
      a2 += g_p3[i][2]; a3 += g_p3[i][3];
    }
    a0 = blockReduce160(a0, sred);
    a1 = blockReduce160(a1, sred);
    a2 = blockReduce160(a2, sred);
    a3 = blockReduce160(a3, sred);
    if (w == 0){
      double loss = fabs(a0 / (a1 + 1e-6)) + fabs(a2 / (a3 + 1e-6));
      out[0] = (float)(2.0 - loss);
      g_cnt3 = 0;   // reset for next graph replay
    }
  }
}

extern "C" void kernel_launch(void* const* d_in, const int* in_sizes, int n_in,
                              void* d_out, int out_size){
  const float* lab = (const float*)d_in[0];   // labels
  const float* inp = (const float*)d_in[1];   // inputs
  k12_convwh<<<NB12, 160>>>(lab, inp);
  k3_convd_reduce<<<NB3, 160>>>(lab, inp, (float*)d_out);
}